// round 3
// baseline (speedup 1.0000x reference)
#include <cuda_runtime.h>

#define RAD   5
#define HI    256
#define WI    256
#define HWSZ  (HI * WI)
#define MAXPIX (8 * HWSZ)

#define TX    32
#define TY    16
#define SW    (TX + 2 * RAD)   /* 42 */
#define SH    (TY + RAD)       /* 21 */
#define NTHR  256

__device__ float4 g_feat[MAXPIX];
__device__ float2 g_mask[MAXPIX];
__device__ float  g_num;
__device__ float  g_den;

// Compile-time exp (Taylor, |x| <= 0.7 here, converges to float precision fast)
__host__ __device__ constexpr float cexp_c(double x) {
    double s = 1.0, t = 1.0;
    for (int i = 1; i < 24; ++i) { t *= x / (double)i; s += t; }
    return (float)s;
}

__global__ void k_init() { g_num = 0.0f; g_den = 0.0f; }

__global__ void k_prep(const float* __restrict__ x, const float* __restrict__ y,
                       const float* __restrict__ msrc, const float* __restrict__ mdst,
                       int NHW) {
    int i = blockIdx.x * blockDim.x + threadIdx.x;
    float md = 0.0f;
    if (i < NHW) {
        int n = i / HWSZ;
        int r = i - n * HWSZ;
        const float* xb = x + (size_t)n * 3 * HWSZ + r;
        float4 f;
        f.x = xb[0];
        f.y = xb[HWSZ];
        f.z = xb[2 * HWSZ];
        float yy = y[i];
        f.w = 1.0f / (1.0f + __expf(-yy));   // sigmoid
        float ms = msrc[i];
        if (!(ms == ms) || ms < 1.0f) ms = 0.0f;   // NaN->0, <1 -> 0, >=1 kept as-is
        md = mdst[i];
        if (!(md == md) || md < 1.0f) md = 0.0f;
        g_feat[i] = f;
        g_mask[i] = make_float2(ms, md);
    }
    // warp-reduce md for denom
    #pragma unroll
    for (int o = 16; o; o >>= 1) md += __shfl_xor_sync(0xffffffffu, md, o);
    if ((threadIdx.x & 31) == 0 && md != 0.0f) atomicAdd(&g_den, md);
}

// One forward offset. O in [0,60): O<5 -> (dy=0, dx=O+1); else dy=(O-5)/11+1, dx=(O-5)%11-5.
template <int O>
struct Step {
    static __device__ __forceinline__ void run(const float4* __restrict__ sf,
                                               const float2* __restrict__ sm,
                                               int base,
                                               float px, float py, float pz,
                                               float bp, float cp,
                                               float& a1, float& a2) {
        constexpr int DY = (O < 5) ? 0 : ((O - 5) / 11 + 1);
        constexpr int DX = (O < 5) ? (O + 1) : ((O - 5) % 11 - 5);
        constexpr float GXY = cexp_c(-(double)(DX * DX + DY * DY) / 72.0);
        constexpr float A = 0.9f * GXY;
        constexpr float B = 0.1f * GXY;
        constexpr int SOFF = DY * SW + DX;

        float4 fq = sf[base + SOFF];
        float2 mq = sm[base + SOFF];
        float d0 = fq.x - px;
        float d1 = fq.y - py;
        float d2 = fq.z - pz;
        float s  = fmaf(d2, d2, fmaf(d1, d1, d0 * d0));
        // exp(-50*s) = exp2(s * (-50*log2(e)))
        float arg = s * (-72.134752044448170f);
        float e;
        asm("ex2.approx.f32 %0, %1;" : "=f"(e) : "f"(arg));
        float K = fmaf(A, e, B);            // g_xy*(0.9*exp + 0.1)
        float w = fmaf(fq.w, cp, bp);       // b_p + b_q - 2 b_p b_q, cp = 1-2*b_p
        float t = K * w;
        a1 = fmaf(t, mq.x, a1);             // * ms_q
        a2 = fmaf(t, mq.y, a2);             // * md_q
    }
};

template <int O, int END>
struct Loop {
    static __device__ __forceinline__ void run(const float4* sf, const float2* sm, int base,
                                               float px, float py, float pz,
                                               float bp, float cp, float& a1, float& a2) {
        Step<O>::run(sf, sm, base, px, py, pz, bp, cp, a1, a2);
        Loop<O + 1, END>::run(sf, sm, base, px, py, pz, bp, cp, a1, a2);
    }
};
template <int END>
struct Loop<END, END> {
    static __device__ __forceinline__ void run(const float4*, const float2*, int,
                                               float, float, float, float, float,
                                               float&, float&) {}
};

__global__ void __launch_bounds__(NTHR) k_main() {
    __shared__ float4 sf[SH * SW];
    __shared__ float2 sm[SH * SW];
    __shared__ float red[NTHR / 32];

    const int tileX = blockIdx.x * TX;
    const int tileY = blockIdx.y * TY;
    const int n = blockIdx.z;
    const int tid = threadIdx.x;
    const int nbase = n * HWSZ;

    // Load tile + halo (left/right 5, bottom 5; no top halo needed for forward offsets)
    for (int i = tid; i < SH * SW; i += NTHR) {
        int ly = i / SW;
        int lx = i - ly * SW;
        int gy = tileY + ly;
        int gx = tileX + lx - RAD;
        float4 f = make_float4(0.f, 0.f, 0.f, 0.f);
        float2 m = make_float2(0.f, 0.f);
        if (gx >= 0 && gx < WI && gy < HI) {
            int gi = nbase + gy * WI + gx;
            f = g_feat[gi];
            m = g_mask[gi];
        }
        sf[i] = f;
        sm[i] = m;
    }
    __syncthreads();

    const int tx  = tid & 31;
    const int ty0 = tid >> 5;   // 0..7, each thread handles rows ty0 and ty0+8

    float total = 0.0f;
    #pragma unroll 1
    for (int k = 0; k < 2; ++k) {
        int py_ = ty0 + k * 8;
        int base = py_ * SW + (tx + RAD);
        float4 fp = sf[base];
        float2 mp = sm[base];
        float cp = 1.0f - 2.0f * fp.w;
        float a1 = 0.0f, a2 = 0.0f;
        Loop<0, 60>::run(sf, sm, base, fp.x, fp.y, fp.z, fp.w, cp, a1, a2);
        // unordered pair counted once, both orderings: md_p*Σt*ms_q + ms_p*Σt*md_q
        total += mp.y * a1 + mp.x * a2;
    }

    // block reduce + atomic
    #pragma unroll
    for (int o = 16; o; o >>= 1) total += __shfl_xor_sync(0xffffffffu, total, o);
    if ((tid & 31) == 0) red[tid >> 5] = total;
    __syncthreads();
    if (tid < NTHR / 32) {
        float v = red[tid];
        #pragma unroll
        for (int o = (NTHR / 64); o; o >>= 1) v += __shfl_xor_sync(0xffffffffu, v, o);
        if (tid == 0) atomicAdd(&g_num, v);
    }
}

__global__ void k_final(float* out) {
    out[0] = g_num / fmaxf(g_den, 1.0f);
}

extern "C" void kernel_launch(void* const* d_in, const int* in_sizes, int n_in,
                              void* d_out, int out_size) {
    const float* x    = (const float*)d_in[0];
    const float* y    = (const float*)d_in[1];
    const float* msrc = (const float*)d_in[2];
    const float* mdst = (const float*)d_in[3];

    int NHW = in_sizes[1];          // y element count = N*H*W
    int N   = NHW / HWSZ;

    k_init<<<1, 1>>>();
    k_prep<<<(NHW + 255) / 256, 256>>>(x, y, msrc, mdst, NHW);
    dim3 grid(WI / TX, HI / TY, N);
    k_main<<<grid, NTHR>>>();
    k_final<<<1, 1>>>((float*)d_out);
}

// round 5
// speedup vs baseline: 1.9322x; 1.9322x over previous
#include <cuda_runtime.h>

#define RAD   5
#define HI    256
#define WI    256
#define HWSZ  (HI * WI)

#define TX    32
#define TY    16
#define SW    (TX + 2 * RAD)   /* 42 */
#define SH    (TY + RAD)       /* 21 */
#define NTHR  256
#define MAXBLK 4096

__device__ float    p_num[MAXBLK];
__device__ float    p_den[MAXBLK];
__device__ unsigned g_count = 0;

// Compile-time exp (Taylor; |x| <= ~0.7 at the evaluated points)
__host__ __device__ constexpr float cexp_c(double x) {
    double s = 1.0, t = 1.0;
    for (int i = 1; i < 24; ++i) { t *= x / (double)i; s += t; }
    return (float)s;
}

// One forward offset. O in [0,60): O<5 -> (dy=0, dx=O+1); else dy=(O-5)/11+1, dx=(O-5)%11-5.
template <int O>
struct Step {
    static __device__ __forceinline__ void run(const float4* __restrict__ sf,
                                               const float2* __restrict__ sm,
                                               int base,
                                               float px, float py, float pz,
                                               float bp, float cp,
                                               float& a1, float& a2) {
        constexpr int DY = (O < 5) ? 0 : ((O - 5) / 11 + 1);
        constexpr int DX = (O < 5) ? (O + 1) : ((O - 5) % 11 - 5);
        constexpr float GXY = cexp_c(-(double)(DX * DX + DY * DY) / 72.0);
        constexpr float A = 0.9f * GXY;
        constexpr float B = 0.1f * GXY;
        constexpr int SOFF = DY * SW + DX;

        float4 fq = sf[base + SOFF];
        float2 mq = sm[base + SOFF];
        float d0 = fq.x - px;
        float d1 = fq.y - py;
        float d2 = fq.z - pz;
        float s  = fmaf(d2, d2, fmaf(d1, d1, d0 * d0));
        float arg = s * (-72.134752044448170f);   // -50*log2(e)
        float e;
        asm("ex2.approx.f32 %0, %1;" : "=f"(e) : "f"(arg));
        float K = fmaf(A, e, B);            // g_xy*(0.9*exp + 0.1)
        float w = fmaf(fq.w, cp, bp);       // b_p + b_q - 2 b_p b_q, cp = 1-2*b_p
        float t = K * w;
        a1 = fmaf(t, mq.x, a1);             // * ms_q
        a2 = fmaf(t, mq.y, a2);             // * md_q
    }
};

template <int O, int END>
struct Loop {
    static __device__ __forceinline__ void run(const float4* sf, const float2* sm, int base,
                                               float px, float py, float pz,
                                               float bp, float cp, float& a1, float& a2) {
        Step<O>::run(sf, sm, base, px, py, pz, bp, cp, a1, a2);
        Loop<O + 1, END>::run(sf, sm, base, px, py, pz, bp, cp, a1, a2);
    }
};
template <int END>
struct Loop<END, END> {
    static __device__ __forceinline__ void run(const float4*, const float2*, int,
                                               float, float, float, float, float,
                                               float&, float&) {}
};

__global__ void __launch_bounds__(NTHR) k_fused(const float* __restrict__ x,
                                                const float* __restrict__ y,
                                                const float* __restrict__ msrc,
                                                const float* __restrict__ mdst,
                                                float* __restrict__ out,
                                                int nblk) {
    __shared__ float4 sf[SH * SW];
    __shared__ float2 sm[SH * SW];
    __shared__ float red[NTHR / 32];
    __shared__ float red2[NTHR / 32];
    __shared__ int   slast;

    const int tileX = blockIdx.x * TX;
    const int tileY = blockIdx.y * TY;
    const int n = blockIdx.z;
    const int tid = threadIdx.x;
    const int bid = (blockIdx.z * gridDim.y + blockIdx.y) * gridDim.x + blockIdx.x;
    const int nbase = n * HWSZ;
    const float* xb = x + (size_t)n * 3 * HWSZ;

    // Load tile + halo directly from global, computing features on the fly.
    for (int i = tid; i < SH * SW; i += NTHR) {
        int ly = i / SW;
        int lx = i - ly * SW;
        int gy = tileY + ly;
        int gx = tileX + lx - RAD;
        float4 f = make_float4(0.f, 0.f, 0.f, 0.f);
        float2 m = make_float2(0.f, 0.f);
        if (gx >= 0 && gx < WI && gy < HI) {
            int r  = gy * WI + gx;
            f.x = xb[r];
            f.y = xb[HWSZ + r];
            f.z = xb[2 * HWSZ + r];
            float yy = y[nbase + r];
            f.w = 1.0f / (1.0f + __expf(-yy));       // sigmoid
            float ms = msrc[nbase + r];
            if (!(ms == ms) || ms < 1.0f) ms = 0.0f; // NaN->0, <1 -> 0
            float md = mdst[nbase + r];
            if (!(md == md) || md < 1.0f) md = 0.0f;
            m = make_float2(ms, md);
        }
        sf[i] = f;
        sm[i] = m;
    }
    __syncthreads();

    const int tx  = tid & 31;
    const int ty0 = tid >> 5;   // 0..7; each thread handles rows ty0 and ty0+8

    float total = 0.0f;
    float den   = 0.0f;
    #pragma unroll 1
    for (int k = 0; k < 2; ++k) {
        int py_ = ty0 + k * 8;
        int base = py_ * SW + (tx + RAD);
        float4 fp = sf[base];
        float2 mp = sm[base];
        float cp = 1.0f - 2.0f * fp.w;
        float a1 = 0.0f, a2 = 0.0f;
        Loop<0, 60>::run(sf, sm, base, fp.x, fp.y, fp.z, fp.w, cp, a1, a2);
        // unordered pair counted once, both orderings: md_p*Σt*ms_q + ms_p*Σt*md_q
        total += mp.y * a1 + mp.x * a2;
        den   += mp.y;                     // denom: binarized md over core pixels
    }

    // block reduce num + den
    #pragma unroll
    for (int o = 16; o; o >>= 1) {
        total += __shfl_xor_sync(0xffffffffu, total, o);
        den   += __shfl_xor_sync(0xffffffffu, den, o);
    }
    if ((tid & 31) == 0) { red[tid >> 5] = total; red2[tid >> 5] = den; }
    __syncthreads();
    if (tid == 0) {
        float vn = 0.0f, vd = 0.0f;
        #pragma unroll
        for (int i = 0; i < NTHR / 32; ++i) { vn += red[i]; vd += red2[i]; }
        p_num[bid] = vn;
        p_den[bid] = vd;
        __threadfence();
        unsigned t = atomicAdd(&g_count, 1u);
        slast = (t == (unsigned)(nblk - 1));
    }
    __syncthreads();

    // Last block: reduce all partials, write result, reset counter.
    if (slast) {
        float vn = 0.0f, vd = 0.0f;
        for (int i = tid; i < nblk; i += NTHR) { vn += p_num[i]; vd += p_den[i]; }
        #pragma unroll
        for (int o = 16; o; o >>= 1) {
            vn += __shfl_xor_sync(0xffffffffu, vn, o);
            vd += __shfl_xor_sync(0xffffffffu, vd, o);
        }
        if ((tid & 31) == 0) { red[tid >> 5] = vn; red2[tid >> 5] = vd; }
        __syncthreads();
        if (tid == 0) {
            float fn = 0.0f, fd = 0.0f;
            #pragma unroll
            for (int i = 0; i < NTHR / 32; ++i) { fn += red[i]; fd += red2[i]; }
            out[0] = fn / fmaxf(fd, 1.0f);
            g_count = 0;    // reset for next graph replay (deterministic)
        }
    }
}

extern "C" void kernel_launch(void* const* d_in, const int* in_sizes, int n_in,
                              void* d_out, int out_size) {
    const float* x    = (const float*)d_in[0];
    const float* y    = (const float*)d_in[1];
    const float* msrc = (const float*)d_in[2];
    const float* mdst = (const float*)d_in[3];

    int NHW = in_sizes[1];          // y element count = N*H*W
    int N   = NHW / HWSZ;

    dim3 grid(WI / TX, HI / TY, N);
    int nblk = grid.x * grid.y * grid.z;
    k_fused<<<grid, NTHR>>>(x, y, msrc, mdst, (float*)d_out, nblk);
}

// round 6
// speedup vs baseline: 1.9655x; 1.0172x over previous
#include <cuda_runtime.h>

#define RAD   5
#define HI    256
#define WI    256
#define HWSZ  (HI * WI)

#define TX    32
#define TY    8
#define SW    (TX + 2 * RAD)   /* 42 */
#define SH    (TY + RAD)       /* 13 */
#define NTHR  256
#define MAXBLK 4096

__device__ float    p_num[MAXBLK];
__device__ float    p_den[MAXBLK];
__device__ unsigned g_count = 0;

// Compile-time exp (Taylor; |x| <= ~0.7 at the evaluated points)
__host__ __device__ constexpr float cexp_c(double x) {
    double s = 1.0, t = 1.0;
    for (int i = 1; i < 24; ++i) { t *= x / (double)i; s += t; }
    return (float)s;
}

// One forward offset. O in [0,60): O<5 -> (dy=0, dx=O+1); else dy=(O-5)/11+1, dx=(O-5)%11-5.
template <int O>
struct Step {
    static __device__ __forceinline__ void run(const float4* __restrict__ sf,
                                               const float2* __restrict__ sm,
                                               int base,
                                               float px, float py, float pz,
                                               float bp, float cp,
                                               float& a1, float& a2) {
        constexpr int DY = (O < 5) ? 0 : ((O - 5) / 11 + 1);
        constexpr int DX = (O < 5) ? (O + 1) : ((O - 5) % 11 - 5);
        constexpr float GXY = cexp_c(-(double)(DX * DX + DY * DY) / 72.0);
        constexpr float A = 0.9f * GXY;
        constexpr float B = 0.1f * GXY;
        constexpr int SOFF = DY * SW + DX;

        float4 fq = sf[base + SOFF];
        float2 mq = sm[base + SOFF];
        float d0 = fq.x - px;
        float d1 = fq.y - py;
        float d2 = fq.z - pz;
        float s  = fmaf(d2, d2, fmaf(d1, d1, d0 * d0));
        float arg = s * (-72.134752044448170f);   // -50*log2(e)
        float e;
        asm("ex2.approx.f32 %0, %1;" : "=f"(e) : "f"(arg));
        float K = fmaf(A, e, B);            // g_xy*(0.9*exp + 0.1)
        float w = fmaf(fq.w, cp, bp);       // b_p + b_q - 2 b_p b_q, cp = 1-2*b_p
        float t = K * w;
        a1 = fmaf(t, mq.x, a1);             // * ms_q
        a2 = fmaf(t, mq.y, a2);             // * md_q
    }
};

template <int O, int END>
struct Loop {
    static __device__ __forceinline__ void run(const float4* sf, const float2* sm, int base,
                                               float px, float py, float pz,
                                               float bp, float cp, float& a1, float& a2) {
        Step<O>::run(sf, sm, base, px, py, pz, bp, cp, a1, a2);
        Loop<O + 1, END>::run(sf, sm, base, px, py, pz, bp, cp, a1, a2);
    }
};
template <int END>
struct Loop<END, END> {
    static __device__ __forceinline__ void run(const float4*, const float2*, int,
                                               float, float, float, float, float,
                                               float&, float&) {}
};

__global__ void __launch_bounds__(NTHR) k_fused(const float* __restrict__ x,
                                                const float* __restrict__ y,
                                                const float* __restrict__ msrc,
                                                const float* __restrict__ mdst,
                                                float* __restrict__ out,
                                                int nblk) {
    __shared__ float4 sf[SH * SW];
    __shared__ float2 sm[SH * SW];
    __shared__ float red[NTHR / 32];
    __shared__ float red2[NTHR / 32];
    __shared__ int   slast;

    const int tileX = blockIdx.x * TX;
    const int tileY = blockIdx.y * TY;
    const int n = blockIdx.z;
    const int tid = threadIdx.x;
    const int bid = (blockIdx.z * gridDim.y + blockIdx.y) * gridDim.x + blockIdx.x;
    const int nbase = n * HWSZ;
    const float* xb = x + (size_t)n * 3 * HWSZ;

    // Load tile + halo directly from global, computing features on the fly.
    for (int i = tid; i < SH * SW; i += NTHR) {
        int ly = i / SW;
        int lx = i - ly * SW;
        int gy = tileY + ly;
        int gx = tileX + lx - RAD;
        float4 f = make_float4(0.f, 0.f, 0.f, 0.f);
        float2 m = make_float2(0.f, 0.f);
        if (gx >= 0 && gx < WI && gy < HI) {
            int r  = gy * WI + gx;
            f.x = xb[r];
            f.y = xb[HWSZ + r];
            f.z = xb[2 * HWSZ + r];
            float yy = y[nbase + r];
            f.w = 1.0f / (1.0f + __expf(-yy));       // sigmoid
            float ms = msrc[nbase + r];
            if (!(ms == ms) || ms < 1.0f) ms = 0.0f; // NaN->0, <1 -> 0
            float md = mdst[nbase + r];
            if (!(md == md) || md < 1.0f) md = 0.0f;
            m = make_float2(ms, md);
        }
        sf[i] = f;
        sm[i] = m;
    }
    __syncthreads();

    const int tx = tid & 31;
    const int ty = tid >> 5;   // 0..7 — one pixel per thread

    const int base = ty * SW + (tx + RAD);
    float4 fp = sf[base];
    float2 mp = sm[base];
    float cp = 1.0f - 2.0f * fp.w;
    float a1 = 0.0f, a2 = 0.0f;
    Loop<0, 60>::run(sf, sm, base, fp.x, fp.y, fp.z, fp.w, cp, a1, a2);
    // unordered pair counted once, both orderings: md_p*Σt*ms_q + ms_p*Σt*md_q
    float total = mp.y * a1 + mp.x * a2;
    float den   = mp.y;                     // denom: binarized md over core pixels

    // block reduce num + den
    #pragma unroll
    for (int o = 16; o; o >>= 1) {
        total += __shfl_xor_sync(0xffffffffu, total, o);
        den   += __shfl_xor_sync(0xffffffffu, den, o);
    }
    if ((tid & 31) == 0) { red[tid >> 5] = total; red2[tid >> 5] = den; }
    __syncthreads();
    if (tid == 0) {
        float vn = 0.0f, vd = 0.0f;
        #pragma unroll
        for (int i = 0; i < NTHR / 32; ++i) { vn += red[i]; vd += red2[i]; }
        p_num[bid] = vn;
        p_den[bid] = vd;
        __threadfence();
        unsigned t = atomicAdd(&g_count, 1u);
        slast = (t == (unsigned)(nblk - 1));
    }
    __syncthreads();

    // Last block: reduce all partials, write result, reset counter.
    if (slast) {
        float vn = 0.0f, vd = 0.0f;
        for (int i = tid; i < nblk; i += NTHR) { vn += p_num[i]; vd += p_den[i]; }
        #pragma unroll
        for (int o = 16; o; o >>= 1) {
            vn += __shfl_xor_sync(0xffffffffu, vn, o);
            vd += __shfl_xor_sync(0xffffffffu, vd, o);
        }
        if ((tid & 31) == 0) { red[tid >> 5] = vn; red2[tid >> 5] = vd; }
        __syncthreads();
        if (tid == 0) {
            float fn = 0.0f, fd = 0.0f;
            #pragma unroll
            for (int i = 0; i < NTHR / 32; ++i) { fn += red[i]; fd += red2[i]; }
            out[0] = fn / fmaxf(fd, 1.0f);
            g_count = 0;    // reset for next graph replay (deterministic)
        }
    }
}

extern "C" void kernel_launch(void* const* d_in, const int* in_sizes, int n_in,
                              void* d_out, int out_size) {
    const float* x    = (const float*)d_in[0];
    const float* y    = (const float*)d_in[1];
    const float* msrc = (const float*)d_in[2];
    const float* mdst = (const float*)d_in[3];

    int NHW = in_sizes[1];          // y element count = N*H*W
    int N   = NHW / HWSZ;

    dim3 grid(WI / TX, HI / TY, N);
    int nblk = grid.x * grid.y * grid.z;
    k_fused<<<grid, NTHR>>>(x, y, msrc, mdst, (float*)d_out, nblk);
}

// round 7
// speedup vs baseline: 1.9826x; 1.0087x over previous
#include <cuda_runtime.h>

#define RAD   5
#define HI    256
#define WI    256
#define HWSZ  (HI * WI)

#define TX    32
#define TY    8
#define SW    (TX + 2 * RAD)   /* 42 */
#define SH    (TY + RAD)       /* 13 */
#define NTHR  128              /* 4 warps; each thread owns 2 vertically adjacent pixels */
#define MAXBLK 4096

__device__ float    p_num[MAXBLK];
__device__ float    p_den[MAXBLK];
__device__ unsigned g_count = 0;

// Compile-time exp (Taylor; |x| <= ~0.7 at the evaluated points)
__host__ __device__ constexpr float cexp_c(double x) {
    double s = 1.0, t = 1.0;
    for (int i = 1; i < 24; ++i) { t *= x / (double)i; s += t; }
    return (float)s;
}

__device__ __forceinline__ void pair_step(float4 fq, float2 mq,
                                          float px, float py, float pz,
                                          float bp, float cp,
                                          float A, float B,
                                          float& a1, float& a2) {
    float d0 = fq.x - px;
    float d1 = fq.y - py;
    float d2 = fq.z - pz;
    float s  = fmaf(d2, d2, fmaf(d1, d1, d0 * d0));
    float arg = s * (-72.134752044448170f);   // -50*log2(e)
    float e;
    asm("ex2.approx.f32 %0, %1;" : "=f"(e) : "f"(arg));
    float K = fmaf(A, e, B);            // g_xy*(0.9*exp + 0.1)
    float w = fmaf(fq.w, cp, bp);       // b_p + b_q - 2 b_p b_q, cp = 1-2*b_p
    float t = K * w;
    a1 = fmaf(t, mq.x, a1);             // * ms_q
    a2 = fmaf(t, mq.y, a2);             // * md_q
}

// L in [0,77): K_ = L/11 (row offset from pixel0), DX = L%11 - 5.
// One shared load serves pixel0 (dy=K_) and pixel1 (dy=K_-1).
template <int L>
struct Step2 {
    static __device__ __forceinline__ void run(const float4* __restrict__ sf,
                                               const float2* __restrict__ sm,
                                               int base0,
                                               float p0x, float p0y, float p0z, float b0, float c0,
                                               float p1x, float p1y, float p1z, float b1, float c1,
                                               float& a10, float& a20, float& a11, float& a21) {
        constexpr int K_ = L / 11;
        constexpr int DX = L % 11 - 5;
        constexpr bool LOADQ = (K_ > 0) || (DX > 0);
        constexpr bool P0 = LOADQ && (K_ <= 5);                       // forward offset for pixel0
        constexpr bool P1 = (K_ >= 2) || (K_ == 1 && DX > 0);         // forward offset for pixel1 (dy=K_-1)
        if constexpr (LOADQ) {
            constexpr int SOFF = K_ * SW + DX;
            float4 fq = sf[base0 + SOFF];
            float2 mq = sm[base0 + SOFF];
            if constexpr (P0) {
                constexpr float GXY = cexp_c(-(double)(DX * DX + K_ * K_) / 72.0);
                pair_step(fq, mq, p0x, p0y, p0z, b0, c0, 0.9f * GXY, 0.1f * GXY, a10, a20);
            }
            if constexpr (P1) {
                constexpr int DY1 = K_ - 1;
                constexpr float GXY = cexp_c(-(double)(DX * DX + DY1 * DY1) / 72.0);
                pair_step(fq, mq, p1x, p1y, p1z, b1, c1, 0.9f * GXY, 0.1f * GXY, a11, a21);
            }
        }
    }
};

template <int L, int END>
struct Loop2 {
    static __device__ __forceinline__ void run(const float4* sf, const float2* sm, int base0,
                                               float p0x, float p0y, float p0z, float b0, float c0,
                                               float p1x, float p1y, float p1z, float b1, float c1,
                                               float& a10, float& a20, float& a11, float& a21) {
        Step2<L>::run(sf, sm, base0, p0x, p0y, p0z, b0, c0, p1x, p1y, p1z, b1, c1,
                      a10, a20, a11, a21);
        Loop2<L + 1, END>::run(sf, sm, base0, p0x, p0y, p0z, b0, c0, p1x, p1y, p1z, b1, c1,
                               a10, a20, a11, a21);
    }
};
template <int END>
struct Loop2<END, END> {
    static __device__ __forceinline__ void run(const float4*, const float2*, int,
                                               float, float, float, float, float,
                                               float, float, float, float, float,
                                               float&, float&, float&, float&) {}
};

__global__ void __launch_bounds__(NTHR) k_fused(const float* __restrict__ x,
                                                const float* __restrict__ y,
                                                const float* __restrict__ msrc,
                                                const float* __restrict__ mdst,
                                                float* __restrict__ out,
                                                int nblk) {
    __shared__ float4 sf[SH * SW];
    __shared__ float2 sm[SH * SW];
    __shared__ float red[NTHR / 32];
    __shared__ float red2[NTHR / 32];
    __shared__ int   slast;

    const int tileX = blockIdx.x * TX;
    const int tileY = blockIdx.y * TY;
    const int n = blockIdx.z;
    const int tid = threadIdx.x;
    const int bid = (blockIdx.z * gridDim.y + blockIdx.y) * gridDim.x + blockIdx.x;
    const int nbase = n * HWSZ;
    const float* xb = x + (size_t)n * 3 * HWSZ;

    // Load tile + halo directly from global, computing features on the fly.
    for (int i = tid; i < SH * SW; i += NTHR) {
        int ly = i / SW;
        int lx = i - ly * SW;
        int gy = tileY + ly;
        int gx = tileX + lx - RAD;
        float4 f = make_float4(0.f, 0.f, 0.f, 0.f);
        float2 m = make_float2(0.f, 0.f);
        if (gx >= 0 && gx < WI && gy < HI) {
            int r  = gy * WI + gx;
            f.x = xb[r];
            f.y = xb[HWSZ + r];
            f.z = xb[2 * HWSZ + r];
            float yy = y[nbase + r];
            f.w = 1.0f / (1.0f + __expf(-yy));       // sigmoid
            float ms = msrc[nbase + r];
            if (!(ms == ms) || ms < 1.0f) ms = 0.0f; // NaN->0, <1 -> 0
            float md = mdst[nbase + r];
            if (!(md == md) || md < 1.0f) md = 0.0f;
            m = make_float2(ms, md);
        }
        sf[i] = f;
        sm[i] = m;
    }
    __syncthreads();

    const int tx = tid & 31;
    const int wy = tid >> 5;              // 0..3 — rows 2*wy and 2*wy+1

    const int base0 = (2 * wy) * SW + (tx + RAD);
    const int base1 = base0 + SW;
    float4 fp0 = sf[base0];
    float2 mp0 = sm[base0];
    float4 fp1 = sf[base1];
    float2 mp1 = sm[base1];
    float c0 = 1.0f - 2.0f * fp0.w;
    float c1 = 1.0f - 2.0f * fp1.w;
    float a10 = 0.0f, a20 = 0.0f, a11 = 0.0f, a21 = 0.0f;
    Loop2<0, 77>::run(sf, sm, base0,
                      fp0.x, fp0.y, fp0.z, fp0.w, c0,
                      fp1.x, fp1.y, fp1.z, fp1.w, c1,
                      a10, a20, a11, a21);
    // unordered pair counted once, both orderings: md_p*Σt*ms_q + ms_p*Σt*md_q
    float total = mp0.y * a10 + mp0.x * a20 + mp1.y * a11 + mp1.x * a21;
    float den   = mp0.y + mp1.y;          // denom: binarized md over core pixels

    // block reduce num + den (4 warps)
    #pragma unroll
    for (int o = 16; o; o >>= 1) {
        total += __shfl_xor_sync(0xffffffffu, total, o);
        den   += __shfl_xor_sync(0xffffffffu, den, o);
    }
    if ((tid & 31) == 0) { red[tid >> 5] = total; red2[tid >> 5] = den; }
    __syncthreads();
    if (tid == 0) {
        float vn = 0.0f, vd = 0.0f;
        #pragma unroll
        for (int i = 0; i < NTHR / 32; ++i) { vn += red[i]; vd += red2[i]; }
        p_num[bid] = vn;
        p_den[bid] = vd;
        __threadfence();
        unsigned t = atomicAdd(&g_count, 1u);
        slast = (t == (unsigned)(nblk - 1));
    }
    __syncthreads();

    // Last block: reduce all partials, write result, reset counter.
    if (slast) {
        float vn = 0.0f, vd = 0.0f;
        for (int i = tid; i < nblk; i += NTHR) { vn += p_num[i]; vd += p_den[i]; }
        #pragma unroll
        for (int o = 16; o; o >>= 1) {
            vn += __shfl_xor_sync(0xffffffffu, vn, o);
            vd += __shfl_xor_sync(0xffffffffu, vd, o);
        }
        if ((tid & 31) == 0) { red[tid >> 5] = vn; red2[tid >> 5] = vd; }
        __syncthreads();
        if (tid == 0) {
            float fn = 0.0f, fd = 0.0f;
            #pragma unroll
            for (int i = 0; i < NTHR / 32; ++i) { fn += red[i]; fd += red2[i]; }
            out[0] = fn / fmaxf(fd, 1.0f);
            g_count = 0;    // reset for next graph replay (deterministic)
        }
    }
}

extern "C" void kernel_launch(void* const* d_in, const int* in_sizes, int n_in,
                              void* d_out, int out_size) {
    const float* x    = (const float*)d_in[0];
    const float* y    = (const float*)d_in[1];
    const float* msrc = (const float*)d_in[2];
    const float* mdst = (const float*)d_in[3];

    int NHW = in_sizes[1];          // y element count = N*H*W
    int N   = NHW / HWSZ;

    dim3 grid(WI / TX, HI / TY, N);
    int nblk = grid.x * grid.y * grid.z;
    k_fused<<<grid, NTHR>>>(x, y, msrc, mdst, (float*)d_out, nblk);
}